// round 14
// baseline (speedup 1.0000x reference)
#include <cuda_runtime.h>
#include <cuda_fp16.h>
#include <cstdint>

#define NPIX 4096
#define CC   256
#define CQ   64
#define BB   8
#define ROWS_ALL 384
#define LD   72    // K/Q row stride (halves)
#define LDS  40    // S/V row stride (halves): 32 data + 8 pad
#define NC   32
#define ITERS (NPIX/NC)
#define LDW  264   // proj W tile stride (halves)
#define LDX  136   // proj x tile stride (halves)
#define LDT  136   // proj transpose-stage stride (halves)

// ================= scratch (device globals) =================
__device__ __half g_Q[(size_t)BB*NPIX*CQ];   // [b][n][cq]
__device__ __half g_K[(size_t)BB*NPIX*CQ];   // [b][m][cq]
__device__ __half g_V[(size_t)BB*CC*NPIX];   // [b][c][n]  (gamma folded)
__device__ __half g_xh[(size_t)BB*CC*NPIX];  // x in fp16, [b][k][n]
__device__ __half g_Wh[ROWS_ALL*CC];         // fused weights fp16 [row][k]
__device__ float  g_ball[ROWS_ALL];

// ================= PTX helpers =================
__device__ __forceinline__ uint32_t smem_u32(const void* p) {
    uint32_t a;
    asm("{ .reg .u64 t; cvta.to.shared.u64 t, %1; cvt.u32.u64 %0, t; }" : "=r"(a) : "l"(p));
    return a;
}
__device__ __forceinline__ void cpa16(uint32_t dst, const void* src) {
    asm volatile("cp.async.cg.shared.global [%0], [%1], 16;" :: "r"(dst), "l"(src));
}
#define CP_COMMIT() asm volatile("cp.async.commit_group;" ::: "memory")
#define CP_WAIT0()  asm volatile("cp.async.wait_group 0;" ::: "memory")

__device__ __forceinline__ void ldsm4(uint32_t r[4], uint32_t addr) {
    asm volatile("ldmatrix.sync.aligned.m8n8.x4.shared.b16 {%0,%1,%2,%3}, [%4];"
        : "=r"(r[0]), "=r"(r[1]), "=r"(r[2]), "=r"(r[3]) : "r"(addr));
}
__device__ __forceinline__ void ldsm4t(uint32_t r[4], uint32_t addr) {
    asm volatile("ldmatrix.sync.aligned.m8n8.x4.trans.shared.b16 {%0,%1,%2,%3}, [%4];"
        : "=r"(r[0]), "=r"(r[1]), "=r"(r[2]), "=r"(r[3]) : "r"(addr));
}
__device__ __forceinline__ void mmah(float c[4], const uint32_t a[4],
                                     uint32_t b0, uint32_t b1) {
    asm volatile(
        "mma.sync.aligned.m16n8k16.row.col.f32.f16.f16.f32 "
        "{%0,%1,%2,%3}, {%4,%5,%6,%7}, {%8,%9}, {%0,%1,%2,%3};"
        : "+f"(c[0]), "+f"(c[1]), "+f"(c[2]), "+f"(c[3])
        : "r"(a[0]), "r"(a[1]), "r"(a[2]), "r"(a[3]), "r"(b0), "r"(b1));
}
__device__ __forceinline__ uint32_t packh(float e0, float e1) {
    uint32_t r; asm("cvt.rn.f16x2.f32 %0, %1, %2;" : "=r"(r) : "f"(e1), "f"(e0)); return r;
}
// elu without /N (deferred), exp via FFMA polynomial
__device__ __forceinline__ float elu_raw(float v) {
    float kf = rintf(v * 1.44269504f);
    float r  = fmaf(kf, -0.693145752f, v);
    r        = fmaf(kf, -1.42860677e-6f, r);
    float p  = 1.38888894e-3f;
    p = fmaf(p, r, 8.33333377e-3f);
    p = fmaf(p, r, 4.16666679e-2f);
    p = fmaf(p, r, 0.166666672f);
    p = fmaf(p, r, 0.5f);
    p = fmaf(p, r, 1.0f);
    p = fmaf(p, r, 1.0f);
    float sc = __uint_as_float((uint32_t)((127 + (int)kf) << 23));
    float e  = fmaf(p, sc, -1.0f);
    return v > 0.f ? v : e;
}

// ================= Kernel 0: weights (gamma folded into V), fp16 out =======
__global__ void build_weights(const float* __restrict__ qw, const float* __restrict__ qb,
                              const float* __restrict__ kw, const float* __restrict__ kb,
                              const float* __restrict__ vw, const float* __restrict__ vb,
                              const float* __restrict__ gw) {
    int r = blockIdx.x, d = threadIdx.x;
    if (r < CQ) {
        g_Wh[r*CC + d] = __float2half(qw[r*CC + d]);
        if (d == 0) g_ball[r] = qb[r];
    } else if (r < 2*CQ) {
        g_Wh[r*CC + d] = __float2half(kw[(r-CQ)*CC + d]);
        if (d == 0) g_ball[r] = kb[r-CQ];
    } else {
        int c = r - 2*CQ;
        float acc = 0.f;
        for (int cp = 0; cp < CC; ++cp) acc = fmaf(gw[c*CC + cp], vw[cp*CC + d], acc);
        g_Wh[r*CC + d] = __float2half(acc);
        if (d == 0) {
            float bacc = 0.f;
            for (int cp = 0; cp < CC; ++cp) bacc = fmaf(gw[c*CC + cp], vb[cp], bacc);
            g_ball[r] = bacc;
        }
    }
}

// ================= Kernel 0b: x -> fp16 =================
__global__ void __launch_bounds__(256) cvt_x(const float* __restrict__ x) {
    size_t nq = (size_t)BB*CC*NPIX / 4;
    for (size_t q = (size_t)blockIdx.x*blockDim.x + threadIdx.x; q < nq;
         q += (size_t)gridDim.x*blockDim.x) {
        float4 v = *(const float4*)(x + q*4);
        uint2 o;
        o.x = packh(v.x, v.y);
        o.y = packh(v.z, v.w);
        *(uint2*)(g_xh + q*4) = o;
    }
}

// ================= Kernel 1: projection via HMMA (unchanged) ===============
#define PW_O 0
#define PX_ST(s) (33792 + (s)*4352)
#define PROJ_SMEM 84992

__global__ void __launch_bounds__(256) proj_mma(const float* __restrict__ unused) {
    extern __shared__ __half psm[];
    const uint32_t sb = smem_u32(psm);
    const int tid = threadIdx.x, wid = tid >> 5, lane = tid & 31;
    const int g = lane >> 2, t4 = lane & 3;
    const int lrow = lane & 15, lcol = (lane >> 4) * 8;
    const int b = blockIdx.z, co0 = blockIdx.y * 128, n0 = blockIdx.x * 128;

    const int wc = (wid & 3) * 32;
    const int wn = (wid >> 2) * 64;

    #define PSB(idx) (sb + (uint32_t)(idx) * 2u)

    {
        const __half* wsrc = g_Wh + (size_t)co0 * CC;
        #pragma unroll
        for (int r = 0; r < 16; r++) {
            int id = tid + 256*r, row = id >> 5, ch = (id & 31) * 8;
            cpa16(PSB(PW_O + row*LDW + ch), wsrc + (size_t)row*CC + ch);
        }
        const __half* xsrc = g_xh + ((size_t)b*CC + 0)*NPIX + n0;
        #pragma unroll
        for (int r = 0; r < 2; r++) {
            int id = tid + 256*r, k = id >> 4, ch = (id & 15) * 8;
            cpa16(PSB(PX_ST(0) + k*LDX + ch), xsrc + (size_t)k*NPIX + ch);
        }
        CP_COMMIT();
    }

    float acc[2][8][4];
    #pragma unroll
    for (int i = 0; i < 2; i++)
        #pragma unroll
        for (int j = 0; j < 8; j++)
            #pragma unroll
            for (int q = 0; q < 4; q++) acc[i][j][q] = 0.f;

    for (int kc = 0; kc < 8; ++kc) {
        const int buf = kc & 1;
        CP_WAIT0();
        __syncthreads();
        if (kc < 7) {
            const __half* xsrc = g_xh + ((size_t)b*CC + (kc+1)*32)*NPIX + n0;
            #pragma unroll
            for (int r = 0; r < 2; r++) {
                int id = tid + 256*r, k = id >> 4, ch = (id & 15) * 8;
                cpa16(PSB(PX_ST(buf^1) + k*LDX + ch), xsrc + (size_t)k*NPIX + ch);
            }
            CP_COMMIT();
        }
        const uint32_t XO = PX_ST(buf);
        #pragma unroll
        for (int ks = 0; ks < 2; ++ks) {
            const int kk = kc*32 + ks*16;
            uint32_t a0[4], a1[4];
            ldsm4(a0, PSB(PW_O + (wc      + lrow)*LDW + kk + lcol));
            ldsm4(a1, PSB(PW_O + (wc + 16 + lrow)*LDW + kk + lcol));
            #pragma unroll
            for (int nt = 0; nt < 4; ++nt) {
                uint32_t bx[4];
                ldsm4t(bx, PSB(XO + (ks*16 + lrow)*LDX + wn + nt*16 + lcol));
                mmah(acc[0][2*nt],   a0, bx[0], bx[1]);
                mmah(acc[0][2*nt+1], a0, bx[2], bx[3]);
                mmah(acc[1][2*nt],   a1, bx[0], bx[1]);
                mmah(acc[1][2*nt+1], a1, bx[2], bx[3]);
            }
        }
        __syncthreads();
    }

    if (co0 >= 128) {
        #pragma unroll
        for (int i = 0; i < 2; i++) {
            #pragma unroll
            for (int h = 0; h < 2; h++) {
                int col = wc + 16*i + g + 8*h;
                int c = co0 - 128 + col;
                float bias = g_ball[co0 + col];
                __half* dst = g_V + ((size_t)b*CC + c)*NPIX + n0;
                #pragma unroll
                for (int j = 0; j < 8; j++) {
                    int n = wn + 8*j + t4*2;
                    *(uint32_t*)(dst + n) =
                        packh(acc[i][j][2*h] + bias, acc[i][j][2*h+1] + bias);
                }
            }
        }
    } else {
        __syncthreads();
        #pragma unroll
        for (int i = 0; i < 2; i++)
            #pragma unroll
            for (int h = 0; h < 2; h++) {
                int col = wc + 16*i + g + 8*h;
                float bias = g_ball[col];
                #pragma unroll
                for (int j = 0; j < 8; j++) {
                    int n = wn + 8*j + t4*2;
                    psm[PW_O + n*LDT + col]     = __float2half(acc[i][j][2*h]   + bias);
                    psm[PW_O + (n+1)*LDT + col] = __float2half(acc[i][j][2*h+1] + bias);
                }
            }
        __syncthreads();
        #pragma unroll
        for (int r = 0; r < 8; r++) {
            int id = tid + 256*r, nl = id >> 4, ch = id & 15;
            uint4 v = *(uint4*)&psm[PW_O + nl*LDT + ch*8];
            size_t nglob = (size_t)b*NPIX + n0 + nl;
            if (ch < 8) *(uint4*)(g_Q + nglob*CQ + ch*8) = v;
            else        *(uint4*)(g_K + nglob*CQ + (ch-8)*8) = v;
        }
    }
}

// ================= Kernel 2: fused attention, lagged one-sync pipeline =====
// smem (halves): K | S x2 | Q x2 | V x3   = 45056 halves = 90112 B
#define SM_K  0
#define S_ST(s) (4608  + (s)*2560)
#define Q_ST(s) (9728  + (s)*2304)
#define V_ST(s) (14336 + (s)*10240)
#define SMEM_HALVES 45056
#define SMEM_BYTES  (SMEM_HALVES*2)

__global__ void __launch_bounds__(256, 2) attn_mma(float* __restrict__ out,
                                                   const float* __restrict__ gbias) {
    extern __shared__ __half sm[];
    const uint32_t sb = smem_u32(sm);
    const int tid = threadIdx.x, wid = tid >> 5, lane = tid & 31;
    const int g = lane >> 2, t4 = lane & 3;
    const int b = blockIdx.y, m0 = blockIdx.x * 64;
    const int lrow = lane & 15, lcol = (lane >> 4) * 8;

    const int w1m = (wid & 3) * 16, w1n = (wid >> 2) * 16;   // GEMM1 [16m x 16n]
    const int w2c = (wid >> 1) * 64, w2m = (wid & 1) * 32;   // GEMM2 [64c x 32m]

    #define SMB(idx) (sb + (uint32_t)(idx) * 2u)

    auto issue_stage = [&](int qs, int vs, int n0s) {
        const __half* q = g_Q + ((size_t)b*NPIX + n0s)*CQ;
        {   // 32 rows x 64 halves = 256 chunks
            int row = tid >> 3, ch = (tid & 7) * 8;
            cpa16(SMB(Q_ST(qs) + row*LD + ch), q + (size_t)row*CQ + ch);
        }
        const __half* v = g_V + (size_t)b*CC*NPIX + n0s;
        #pragma unroll
        for (int r = 0; r < 4; r++) {   // 256 rows x 32 halves = 1024 chunks
            int id = tid + 256*r, row = id >> 2, ch = (id & 3) * 8;
            cpa16(SMB(V_ST(vs) + row*LDS + ch), v + (size_t)row*NPIX + ch);
        }
    };

    {   // prologue: K + stage 0 (one group)
        const __half* k = g_K + ((size_t)b*NPIX + m0)*CQ;
        #pragma unroll
        for (int r = 0; r < 2; r++) {
            int id = tid + 256*r, row = id >> 3, ch = (id & 7) * 8;
            cpa16(SMB(SM_K + row*LD + ch), k + (size_t)row*CQ + ch);
        }
        issue_stage(0, 0, 0);
        CP_COMMIT();
    }

    float acc[4][4][4];
    #pragma unroll
    for (int i = 0; i < 4; i++)
        #pragma unroll
        for (int j = 0; j < 4; j++)
            #pragma unroll
            for (int q = 0; q < 4; q++) acc[i][j][q] = 0.f;

    int vcur = 0;   // V buffer index of iter it
    for (int it = 0; it < ITERS; ++it) {
        CP_WAIT0();        // stage it landed (this thread's part)
        __syncthreads();   // all threads' stage it visible; S[it&1] free; V[(it+1)%3] free
        int vnext = vcur + 1; if (vnext == 3) vnext = 0;
        if (it < ITERS-1) {
            issue_stage((it+1) & 1, vnext, (it+1) * NC);
            CP_COMMIT();
        }

        // ---- GEMM2(it-1): O[c][m] += V(it-1)·S(it-1) ----
        if (it > 0) {
            int vp = vcur - 1; if (vp < 0) vp = 2;
            const uint32_t VO = V_ST(vp), SO = S_ST((it-1) & 1);
            #pragma unroll
            for (int kk = 0; kk < 2; kk++) {
                const int C = kk * 16 + lcol;
                uint32_t vv[4][4], s0[4], s1[4];
                #pragma unroll
                for (int i = 0; i < 4; i++)
                    ldsm4(vv[i], SMB(VO + (w2c + 16*i + lrow)*LDS + C));
                ldsm4(s0, SMB(SO + (w2m      + lrow)*LDS + C));
                ldsm4(s1, SMB(SO + (w2m + 16 + lrow)*LDS + C));
                #pragma unroll
                for (int i = 0; i < 4; i++) {
                    mmah(acc[i][0], vv[i], s0[0], s0[2]);
                    mmah(acc[i][1], vv[i], s0[1], s0[3]);
                    mmah(acc[i][2], vv[i], s1[0], s1[2]);
                    mmah(acc[i][3], vv[i], s1[1], s1[3]);
                }
            }
        }

        // ---- GEMM1(it): S[m][n] = K·Q ----
        {
            const uint32_t QO = Q_ST(it & 1);
            float sacc[2][4];
            #pragma unroll
            for (int j = 0; j < 2; j++)
                #pragma unroll
                for (int q = 0; q < 4; q++) sacc[j][q] = 0.f;

            #pragma unroll
            for (int kk = 0; kk < 4; kk++) {
                const int C = kk * 16 + lcol;
                uint32_t kv[4], qv[4];
                ldsm4(kv, SMB(SM_K + (w1m + lrow)*LD + C));
                ldsm4(qv, SMB(QO   + (w1n + lrow)*LD + C));
                mmah(sacc[0], kv, qv[0], qv[2]);
                mmah(sacc[1], kv, qv[1], qv[3]);
            }

            // elu + store S[it&1], layout [m][n], stride LDS
            const uint32_t SW = S_ST(it & 1);
            #pragma unroll
            for (int j = 0; j < 2; j++) {
                int row = w1m + g;
                int col = w1n + 8*j + t4*2;
                *(uint32_t*)&sm[SW + row*LDS + col] =
                    packh(elu_raw(sacc[j][0]), elu_raw(sacc[j][1]));
                *(uint32_t*)&sm[SW + (row+8)*LDS + col] =
                    packh(elu_raw(sacc[j][2]), elu_raw(sacc[j][3]));
            }
        }
        vcur = vnext;
    }

    // ---- drain: GEMM2(ITERS-1) ----
    __syncthreads();   // last S stores visible
    {
        const int vp = (ITERS - 1) % 3;
        const uint32_t VO = V_ST(vp), SO = S_ST((ITERS-1) & 1);
        #pragma unroll
        for (int kk = 0; kk < 2; kk++) {
            const int C = kk * 16 + lcol;
            uint32_t vv[4][4], s0[4], s1[4];
            #pragma unroll
            for (int i = 0; i < 4; i++)
                ldsm4(vv[i], SMB(VO + (w2c + 16*i + lrow)*LDS + C));
            ldsm4(s0, SMB(SO + (w2m      + lrow)*LDS + C));
            ldsm4(s1, SMB(SO + (w2m + 16 + lrow)*LDS + C));
            #pragma unroll
            for (int i = 0; i < 4; i++) {
                mmah(acc[i][0], vv[i], s0[0], s0[2]);
                mmah(acc[i][1], vv[i], s0[1], s0[3]);
                mmah(acc[i][2], vv[i], s1[0], s1[2]);
                mmah(acc[i][3], vv[i], s1[1], s1[3]);
            }
        }
    }

    // ---- epilogue: out = acc/4096 + gbias[c] ----
    const float inv = 1.0f / 4096.0f;
    #pragma unroll
    for (int i = 0; i < 4; i++) {
        int c  = w2c + 16*i + g;
        float b0 = gbias[c], b8 = gbias[c + 8];
        #pragma unroll
        for (int j = 0; j < 4; j++) {
            int m = m0 + w2m + 8*j + t4*2;
            float2 v0 = { fmaf(acc[i][j][0], inv, b0), fmaf(acc[i][j][1], inv, b0) };
            *(float2*)&out[((size_t)b*CC + c)*NPIX + m] = v0;
            float2 v1 = { fmaf(acc[i][j][2], inv, b8), fmaf(acc[i][j][3], inv, b8) };
            *(float2*)&out[((size_t)b*CC + c + 8)*NPIX + m] = v1;
        }
    }
}

// ================= launch =================
extern "C" void kernel_launch(void* const* d_in, const int* in_sizes, int n_in,
                              void* d_out, int out_size) {
    const float* x  = (const float*)d_in[0];
    const float* qw = (const float*)d_in[1];
    const float* qb = (const float*)d_in[2];
    const float* kw = (const float*)d_in[3];
    const float* kb = (const float*)d_in[4];
    const float* vw = (const float*)d_in[5];
    const float* vb = (const float*)d_in[6];
    const float* gw = (const float*)d_in[7];
    const float* gb = (const float*)d_in[8];
    float* out = (float*)d_out;

    cudaFuncSetAttribute(attn_mma, cudaFuncAttributeMaxDynamicSharedMemorySize, SMEM_BYTES);
    cudaFuncSetAttribute(proj_mma, cudaFuncAttributeMaxDynamicSharedMemorySize, PROJ_SMEM);

    build_weights<<<ROWS_ALL, 256>>>(qw, qb, kw, kb, vw, vb, gw);
    cvt_x<<<2048, 256>>>(x);
    proj_mma<<<dim3(32, 3, BB), 256, PROJ_SMEM>>>(nullptr);
    attn_mma<<<dim3(64, BB), 256, SMEM_BYTES>>>(out, gb);
}

// round 15
// speedup vs baseline: 1.2140x; 1.2140x over previous
#include <cuda_runtime.h>
#include <cuda_fp16.h>
#include <cstdint>

#define NPIX 4096
#define CC   256
#define CQ   64
#define BB   8
#define ROWS_ALL 384
#define LD   72    // attn smem row stride (halves)
#define LDW  264   // proj W tile stride (halves)
#define LDX  136   // proj x tile stride (halves)
#define LDT  136   // proj transpose-stage stride (halves)

// ================= scratch (device globals) =================
__device__ __half g_Q[(size_t)BB*NPIX*CQ];   // [b][n][cq]
__device__ __half g_K[(size_t)BB*NPIX*CQ];   // [b][m][cq]
__device__ __half g_V[(size_t)BB*CC*NPIX];   // [b][c][n]  (gamma folded)
__device__ __half g_xh[(size_t)BB*CC*NPIX];  // x in fp16, [b][k][n]
__device__ __half g_Wh[ROWS_ALL*CC];         // fused weights fp16 [row][k]
__device__ float  g_ball[ROWS_ALL];

// ================= PTX helpers =================
__device__ __forceinline__ uint32_t smem_u32(const void* p) {
    uint32_t a;
    asm("{ .reg .u64 t; cvta.to.shared.u64 t, %1; cvt.u32.u64 %0, t; }" : "=r"(a) : "l"(p));
    return a;
}
__device__ __forceinline__ void cpa16(uint32_t dst, const void* src) {
    asm volatile("cp.async.cg.shared.global [%0], [%1], 16;" :: "r"(dst), "l"(src));
}
#define CP_COMMIT() asm volatile("cp.async.commit_group;" ::: "memory")
#define CP_WAIT0()  asm volatile("cp.async.wait_group 0;" ::: "memory")

__device__ __forceinline__ void ldsm4(uint32_t r[4], uint32_t addr) {
    asm volatile("ldmatrix.sync.aligned.m8n8.x4.shared.b16 {%0,%1,%2,%3}, [%4];"
        : "=r"(r[0]), "=r"(r[1]), "=r"(r[2]), "=r"(r[3]) : "r"(addr));
}
__device__ __forceinline__ void ldsm4t(uint32_t r[4], uint32_t addr) {
    asm volatile("ldmatrix.sync.aligned.m8n8.x4.trans.shared.b16 {%0,%1,%2,%3}, [%4];"
        : "=r"(r[0]), "=r"(r[1]), "=r"(r[2]), "=r"(r[3]) : "r"(addr));
}
__device__ __forceinline__ void mmah(float c[4], const uint32_t a[4],
                                     uint32_t b0, uint32_t b1) {
    asm volatile(
        "mma.sync.aligned.m16n8k16.row.col.f32.f16.f16.f32 "
        "{%0,%1,%2,%3}, {%4,%5,%6,%7}, {%8,%9}, {%0,%1,%2,%3};"
        : "+f"(c[0]), "+f"(c[1]), "+f"(c[2]), "+f"(c[3])
        : "r"(a[0]), "r"(a[1]), "r"(a[2]), "r"(a[3]), "r"(b0), "r"(b1));
}
__device__ __forceinline__ uint32_t packh(float e0, float e1) {
    uint32_t r; asm("cvt.rn.f16x2.f32 %0, %1, %2;" : "=r"(r) : "f"(e1), "f"(e0)); return r;
}
// elu without /N (deferred): MUFU-based exp (4 instr vs 15 for the polynomial)
__device__ __forceinline__ float elu_raw(float v) {
    float e;
    asm("ex2.approx.f32 %0, %1;" : "=f"(e) : "f"(v * 1.44269504f));
    return v > 0.f ? v : e - 1.0f;
}

// ================= Kernel 0: weights (gamma folded into V), fp16 out =======
__global__ void build_weights(const float* __restrict__ qw, const float* __restrict__ qb,
                              const float* __restrict__ kw, const float* __restrict__ kb,
                              const float* __restrict__ vw, const float* __restrict__ vb,
                              const float* __restrict__ gw) {
    int r = blockIdx.x, d = threadIdx.x;
    if (r < CQ) {
        g_Wh[r*CC + d] = __float2half(qw[r*CC + d]);
        if (d == 0) g_ball[r] = qb[r];
    } else if (r < 2*CQ) {
        g_Wh[r*CC + d] = __float2half(kw[(r-CQ)*CC + d]);
        if (d == 0) g_ball[r] = kb[r-CQ];
    } else {
        int c = r - 2*CQ;
        float acc = 0.f;
        for (int cp = 0; cp < CC; ++cp) acc = fmaf(gw[c*CC + cp], vw[cp*CC + d], acc);
        g_Wh[r*CC + d] = __float2half(acc);
        if (d == 0) {
            float bacc = 0.f;
            for (int cp = 0; cp < CC; ++cp) bacc = fmaf(gw[c*CC + cp], vb[cp], bacc);
            g_ball[r] = bacc;
        }
    }
}

// ================= Kernel 0b: x -> fp16 =================
__global__ void __launch_bounds__(256) cvt_x(const float* __restrict__ x) {
    size_t nq = (size_t)BB*CC*NPIX / 4;
    for (size_t q = (size_t)blockIdx.x*blockDim.x + threadIdx.x; q < nq;
         q += (size_t)gridDim.x*blockDim.x) {
        float4 v = *(const float4*)(x + q*4);
        uint2 o;
        o.x = packh(v.x, v.y);
        o.y = packh(v.z, v.w);
        *(uint2*)(g_xh + q*4) = o;
    }
}

// ================= Kernel 1: projection via HMMA (unchanged) ===============
#define PW_O 0
#define PX_ST(s) (33792 + (s)*4352)
#define PROJ_SMEM 84992

__global__ void __launch_bounds__(256) proj_mma(const float* __restrict__ unused) {
    extern __shared__ __half psm[];
    const uint32_t sb = smem_u32(psm);
    const int tid = threadIdx.x, wid = tid >> 5, lane = tid & 31;
    const int g = lane >> 2, t4 = lane & 3;
    const int lrow = lane & 15, lcol = (lane >> 4) * 8;
    const int b = blockIdx.z, co0 = blockIdx.y * 128, n0 = blockIdx.x * 128;

    const int wc = (wid & 3) * 32;
    const int wn = (wid >> 2) * 64;

    #define PSB(idx) (sb + (uint32_t)(idx) * 2u)

    {
        const __half* wsrc = g_Wh + (size_t)co0 * CC;
        #pragma unroll
        for (int r = 0; r < 16; r++) {
            int id = tid + 256*r, row = id >> 5, ch = (id & 31) * 8;
            cpa16(PSB(PW_O + row*LDW + ch), wsrc + (size_t)row*CC + ch);
        }
        const __half* xsrc = g_xh + ((size_t)b*CC + 0)*NPIX + n0;
        #pragma unroll
        for (int r = 0; r < 2; r++) {
            int id = tid + 256*r, k = id >> 4, ch = (id & 15) * 8;
            cpa16(PSB(PX_ST(0) + k*LDX + ch), xsrc + (size_t)k*NPIX + ch);
        }
        CP_COMMIT();
    }

    float acc[2][8][4];
    #pragma unroll
    for (int i = 0; i < 2; i++)
        #pragma unroll
        for (int j = 0; j < 8; j++)
            #pragma unroll
            for (int q = 0; q < 4; q++) acc[i][j][q] = 0.f;

    for (int kc = 0; kc < 8; ++kc) {
        const int buf = kc & 1;
        CP_WAIT0();
        __syncthreads();
        if (kc < 7) {
            const __half* xsrc = g_xh + ((size_t)b*CC + (kc+1)*32)*NPIX + n0;
            #pragma unroll
            for (int r = 0; r < 2; r++) {
                int id = tid + 256*r, k = id >> 4, ch = (id & 15) * 8;
                cpa16(PSB(PX_ST(buf^1) + k*LDX + ch), xsrc + (size_t)k*NPIX + ch);
            }
            CP_COMMIT();
        }
        const uint32_t XO = PX_ST(buf);
        #pragma unroll
        for (int ks = 0; ks < 2; ++ks) {
            const int kk = kc*32 + ks*16;
            uint32_t a0[4], a1[4];
            ldsm4(a0, PSB(PW_O + (wc      + lrow)*LDW + kk + lcol));
            ldsm4(a1, PSB(PW_O + (wc + 16 + lrow)*LDW + kk + lcol));
            #pragma unroll
            for (int nt = 0; nt < 4; ++nt) {
                uint32_t bx[4];
                ldsm4t(bx, PSB(XO + (ks*16 + lrow)*LDX + wn + nt*16 + lcol));
                mmah(acc[0][2*nt],   a0, bx[0], bx[1]);
                mmah(acc[0][2*nt+1], a0, bx[2], bx[3]);
                mmah(acc[1][2*nt],   a1, bx[0], bx[1]);
                mmah(acc[1][2*nt+1], a1, bx[2], bx[3]);
            }
        }
        __syncthreads();
    }

    if (co0 >= 128) {
        #pragma unroll
        for (int i = 0; i < 2; i++) {
            #pragma unroll
            for (int h = 0; h < 2; h++) {
                int col = wc + 16*i + g + 8*h;
                int c = co0 - 128 + col;
                float bias = g_ball[co0 + col];
                __half* dst = g_V + ((size_t)b*CC + c)*NPIX + n0;
                #pragma unroll
                for (int j = 0; j < 8; j++) {
                    int n = wn + 8*j + t4*2;
                    *(uint32_t*)(dst + n) =
                        packh(acc[i][j][2*h] + bias, acc[i][j][2*h+1] + bias);
                }
            }
        }
    } else {
        __syncthreads();
        #pragma unroll
        for (int i = 0; i < 2; i++)
            #pragma unroll
            for (int h = 0; h < 2; h++) {
                int col = wc + 16*i + g + 8*h;
                float bias = g_ball[col];
                #pragma unroll
                for (int j = 0; j < 8; j++) {
                    int n = wn + 8*j + t4*2;
                    psm[PW_O + n*LDT + col]     = __float2half(acc[i][j][2*h]   + bias);
                    psm[PW_O + (n+1)*LDT + col] = __float2half(acc[i][j][2*h+1] + bias);
                }
            }
        __syncthreads();
        #pragma unroll
        for (int r = 0; r < 8; r++) {
            int id = tid + 256*r, nl = id >> 4, ch = id & 15;
            uint4 v = *(uint4*)&psm[PW_O + nl*LDT + ch*8];
            size_t nglob = (size_t)b*NPIX + n0 + nl;
            if (ch < 8) *(uint4*)(g_Q + nglob*CQ + ch*8) = v;
            else        *(uint4*)(g_K + nglob*CQ + (ch-8)*8) = v;
        }
    }
}

// ================= Kernel 2: fused attention (R12 structure, MUFU elu) =====
#define SM_K  0
#define SM_S  4608
#define Q_ST(s) (9216 + (s)*4608)
#define V_ST(s) (18432 + (s)*18432)
#define SMEM_HALVES (18432 + 2*18432)
#define SMEM_BYTES  (SMEM_HALVES*2)

__global__ void __launch_bounds__(256) attn_mma(float* __restrict__ out,
                                                const float* __restrict__ gbias) {
    extern __shared__ __half sm[];
    const uint32_t sb = smem_u32(sm);
    const int tid = threadIdx.x, wid = tid >> 5, lane = tid & 31;
    const int g = lane >> 2, t4 = lane & 3;
    const int b = blockIdx.y, m0 = blockIdx.x * 64;
    const int lrow = lane & 15, lcol = (lane >> 4) * 8;

    const int w1m = (wid & 1) * 32, w1n = (wid >> 1) * 16;   // GEMM1 [32m x 16n]
    const int w2c = (wid >> 1) * 64, w2m = (wid & 1) * 32;   // GEMM2 [64c x 32m]

    #define SMB(idx) (sb + (uint32_t)(idx) * 2u)

    auto issue_stage = [&](int s, int n0s) {
        const __half* q = g_Q + ((size_t)b*NPIX + n0s)*CQ;
        #pragma unroll
        for (int r = 0; r < 2; r++) {
            int id = tid + 256*r, row = id >> 3, ch = (id & 7) * 8;
            cpa16(SMB(Q_ST(s) + row*LD + ch), q + (size_t)row*CQ + ch);
        }
        const __half* v = g_V + (size_t)b*CC*NPIX + n0s;
        #pragma unroll
        for (int r = 0; r < 8; r++) {
            int id = tid + 256*r, row = id >> 3, ch = (id & 7) * 8;
            cpa16(SMB(V_ST(s) + row*LD + ch), v + (size_t)row*NPIX + ch);
        }
    };

    {   // K prologue (group 0, with stage 0)
        const __half* k = g_K + ((size_t)b*NPIX + m0)*CQ;
        #pragma unroll
        for (int r = 0; r < 2; r++) {
            int id = tid + 256*r, row = id >> 3, ch = (id & 7) * 8;
            cpa16(SMB(SM_K + row*LD + ch), k + (size_t)row*CQ + ch);
        }
    }
    issue_stage(0, 0);
    CP_COMMIT();

    float acc[4][4][4];
    #pragma unroll
    for (int i = 0; i < 4; i++)
        #pragma unroll
        for (int j = 0; j < 4; j++)
            #pragma unroll
            for (int q = 0; q < 4; q++) acc[i][j][q] = 0.f;

    for (int it = 0; it < 64; ++it) {
        const int buf = it & 1;
        CP_WAIT0();
        __syncthreads();
        if (it < 63) { issue_stage(buf ^ 1, (it + 1) * 64); CP_COMMIT(); }

        const uint32_t QO = Q_ST(buf), VO = V_ST(buf);

        // ---- GEMM1: S[m][n] = K·Q ----
        float sacc[2][2][4];
        #pragma unroll
        for (int i = 0; i < 2; i++)
            #pragma unroll
            for (int j = 0; j < 2; j++)
                #pragma unroll
                for (int q = 0; q < 4; q++) sacc[i][j][q] = 0.f;

        #pragma unroll
        for (int kk = 0; kk < 4; kk++) {
            const int C = kk * 16 + lcol;
            uint32_t k0[4], k1[4], qv[4];
            ldsm4(k0, SMB(SM_K + (w1m      + lrow)*LD + C));
            ldsm4(k1, SMB(SM_K + (w1m + 16 + lrow)*LD + C));
            ldsm4(qv, SMB(QO   + (w1n      + lrow)*LD + C));
            mmah(sacc[0][0], k0, qv[0], qv[2]);
            mmah(sacc[0][1], k0, qv[1], qv[3]);
            mmah(sacc[1][0], k1, qv[0], qv[2]);
            mmah(sacc[1][1], k1, qv[1], qv[3]);
        }

        // ---- elu + store S (fp16), layout [m][n] ----
        #pragma unroll
        for (int i = 0; i < 2; i++)
            #pragma unroll
            for (int j = 0; j < 2; j++) {
                int row = w1m + 16*i + g;
                int col = w1n + 8*j + t4*2;
                *(uint32_t*)&sm[SM_S + row*LD + col] =
                    packh(elu_raw(sacc[i][j][0]), elu_raw(sacc[i][j][1]));
                *(uint32_t*)&sm[SM_S + (row+8)*LD + col] =
                    packh(elu_raw(sacc[i][j][2]), elu_raw(sacc[i][j][3]));
            }
        __syncthreads();

        // ---- GEMM2: O[c][m] += V·S ----
        #pragma unroll
        for (int kk = 0; kk < 4; kk++) {
            const int C = kk * 16 + lcol;
            uint32_t vv[4][4], s0[4], s1[4];
            #pragma unroll
            for (int i = 0; i < 4; i++)
                ldsm4(vv[i], SMB(VO + (w2c + 16*i + lrow)*LD + C));
            ldsm4(s0, SMB(SM_S + (w2m      + lrow)*LD + C));
            ldsm4(s1, SMB(SM_S + (w2m + 16 + lrow)*LD + C));
            #pragma unroll
            for (int i = 0; i < 4; i++) {
                mmah(acc[i][0], vv[i], s0[0], s0[2]);
                mmah(acc[i][1], vv[i], s0[1], s0[3]);
                mmah(acc[i][2], vv[i], s1[0], s1[2]);
                mmah(acc[i][3], vv[i], s1[1], s1[3]);
            }
        }
    }

    // ---- epilogue: out = acc/4096 + gbias[c] ----
    const float inv = 1.0f / 4096.0f;
    #pragma unroll
    for (int i = 0; i < 4; i++) {
        int c  = w2c + 16*i + g;
        float b0 = gbias[c], b8 = gbias[c + 8];
        #pragma unroll
        for (int j = 0; j < 4; j++) {
            int m = m0 + w2m + 8*j + t4*2;
            float2 v0 = { fmaf(acc[i][j][0], inv, b0), fmaf(acc[i][j][1], inv, b0) };
            *(float2*)&out[((size_t)b*CC + c)*NPIX + m] = v0;
            float2 v1 = { fmaf(acc[i][j][2], inv, b8), fmaf(acc[i][j][3], inv, b8) };
            *(float2*)&out[((size_t)b*CC + c + 8)*NPIX + m] = v1;
        }
    }
}

// ================= launch =================
extern "C" void kernel_launch(void* const* d_in, const int* in_sizes, int n_in,
                              void* d_out, int out_size) {
    const float* x  = (const float*)d_in[0];
    const float* qw = (const float*)d_in[1];
    const float* qb = (const float*)d_in[2];
    const float* kw = (const float*)d_in[3];
    const float* kb = (const float*)d_in[4];
    const float* vw = (const float*)d_in[5];
    const float* vb = (const float*)d_in[6];
    const float* gw = (const float*)d_in[7];
    const float* gb = (const float*)d_in[8];
    float* out = (float*)d_out;

    cudaFuncSetAttribute(attn_mma, cudaFuncAttributeMaxDynamicSharedMemorySize, SMEM_BYTES);
    cudaFuncSetAttribute(proj_mma, cudaFuncAttributeMaxDynamicSharedMemorySize, PROJ_SMEM);

    build_weights<<<ROWS_ALL, 256>>>(qw, qb, kw, kb, vw, vb, gw);
    cvt_x<<<2048, 256>>>(x);
    proj_mma<<<dim3(32, 3, BB), 256, PROJ_SMEM>>>(nullptr);
    attn_mma<<<dim3(64, BB), 256, SMEM_BYTES>>>(out, gb);
}

// round 16
// speedup vs baseline: 1.2265x; 1.0103x over previous
#include <cuda_runtime.h>
#include <cuda_fp16.h>
#include <cstdint>

#define NPIX 4096
#define CC   256
#define CQ   64
#define BB   8
#define ROWS_ALL 384
#define LD   72    // attn smem row stride (halves)
#define LDW  264   // proj W tile stride (halves)
#define LDX  136   // proj x tile stride (halves)
#define LDT  136   // proj transpose-stage stride (halves)

// ================= scratch (device globals) =================
__device__ __half g_Q[(size_t)BB*NPIX*CQ];   // [b][n][cq]
__device__ __half g_K[(size_t)BB*NPIX*CQ];   // [b][m][cq]
__device__ __half g_V[(size_t)BB*CC*NPIX];   // [b][c][n]  (gamma folded)
__device__ __half g_xh[(size_t)BB*CC*NPIX];  // x in fp16, [b][k][n]
__device__ __half g_Wh[ROWS_ALL*CC];         // fused weights fp16 [row][k]
__device__ float  g_ball[ROWS_ALL];

// ================= PTX helpers =================
__device__ __forceinline__ uint32_t smem_u32(const void* p) {
    uint32_t a;
    asm("{ .reg .u64 t; cvta.to.shared.u64 t, %1; cvt.u32.u64 %0, t; }" : "=r"(a) : "l"(p));
    return a;
}
__device__ __forceinline__ void cpa16(uint32_t dst, const void* src) {
    asm volatile("cp.async.cg.shared.global [%0], [%1], 16;" :: "r"(dst), "l"(src));
}
#define CP_COMMIT() asm volatile("cp.async.commit_group;" ::: "memory")
#define CP_WAIT0()  asm volatile("cp.async.wait_group 0;" ::: "memory")

__device__ __forceinline__ void ldsm4(uint32_t r[4], uint32_t addr) {
    asm volatile("ldmatrix.sync.aligned.m8n8.x4.shared.b16 {%0,%1,%2,%3}, [%4];"
        : "=r"(r[0]), "=r"(r[1]), "=r"(r[2]), "=r"(r[3]) : "r"(addr));
}
__device__ __forceinline__ void ldsm4t(uint32_t r[4], uint32_t addr) {
    asm volatile("ldmatrix.sync.aligned.m8n8.x4.trans.shared.b16 {%0,%1,%2,%3}, [%4];"
        : "=r"(r[0]), "=r"(r[1]), "=r"(r[2]), "=r"(r[3]) : "r"(addr));
}
__device__ __forceinline__ void mmah(float c[4], const uint32_t a[4],
                                     uint32_t b0, uint32_t b1) {
    asm volatile(
        "mma.sync.aligned.m16n8k16.row.col.f32.f16.f16.f32 "
        "{%0,%1,%2,%3}, {%4,%5,%6,%7}, {%8,%9}, {%0,%1,%2,%3};"
        : "+f"(c[0]), "+f"(c[1]), "+f"(c[2]), "+f"(c[3])
        : "r"(a[0]), "r"(a[1]), "r"(a[2]), "r"(a[3]), "r"(b0), "r"(b1));
}
__device__ __forceinline__ uint32_t packh(float e0, float e1) {
    uint32_t r; asm("cvt.rn.f16x2.f32 %0, %1, %2;" : "=r"(r) : "f"(e1), "f"(e0)); return r;
}
// elu without /N (deferred): MUFU-based exp
__device__ __forceinline__ float elu_raw(float v) {
    float e;
    asm("ex2.approx.f32 %0, %1;" : "=f"(e) : "f"(v * 1.44269504f));
    return v > 0.f ? v : e - 1.0f;
}

// ============ Kernel 0: fused weights-build (gamma@V) + x->fp16 ============
__global__ void __launch_bounds__(256) prep_kernel(
        const float* __restrict__ x,
        const float* __restrict__ qw, const float* __restrict__ qb,
        const float* __restrict__ kw, const float* __restrict__ kb,
        const float* __restrict__ vw, const float* __restrict__ vb,
        const float* __restrict__ gw) {
    int bid = blockIdx.x;
    if (bid < ROWS_ALL) {
        int r = bid, d = threadIdx.x;
        if (r < CQ) {
            g_Wh[r*CC + d] = __float2half(qw[r*CC + d]);
            if (d == 0) g_ball[r] = qb[r];
        } else if (r < 2*CQ) {
            g_Wh[r*CC + d] = __float2half(kw[(r-CQ)*CC + d]);
            if (d == 0) g_ball[r] = kb[r-CQ];
        } else {
            int c = r - 2*CQ;
            float a0 = 0.f, a1 = 0.f, a2 = 0.f, a3 = 0.f;
            #pragma unroll 4
            for (int cp = 0; cp < CC; cp += 4) {
                a0 = fmaf(gw[c*CC + cp    ], vw[(cp    )*CC + d], a0);
                a1 = fmaf(gw[c*CC + cp + 1], vw[(cp + 1)*CC + d], a1);
                a2 = fmaf(gw[c*CC + cp + 2], vw[(cp + 2)*CC + d], a2);
                a3 = fmaf(gw[c*CC + cp + 3], vw[(cp + 3)*CC + d], a3);
            }
            g_Wh[r*CC + d] = __float2half((a0 + a1) + (a2 + a3));
            if (d == 0) {
                float b0 = 0.f, b1 = 0.f;
                #pragma unroll 4
                for (int cp = 0; cp < CC; cp += 2) {
                    b0 = fmaf(gw[c*CC + cp],     vb[cp],     b0);
                    b1 = fmaf(gw[c*CC + cp + 1], vb[cp + 1], b1);
                }
                g_ball[r] = b0 + b1;
            }
        }
    } else {
        // cvt region: 2048 blocks
        size_t nq = (size_t)BB*CC*NPIX / 4;
        size_t base = (size_t)(bid - ROWS_ALL)*blockDim.x + threadIdx.x;
        for (size_t q = base; q < nq; q += (size_t)2048*blockDim.x) {
            float4 v = *(const float4*)(x + q*4);
            uint2 o;
            o.x = packh(v.x, v.y);
            o.y = packh(v.z, v.w);
            *(uint2*)(g_xh + q*4) = o;
        }
    }
}

// ================= Kernel 1: projection via HMMA (unchanged) ===============
#define PW_O 0
#define PX_ST(s) (33792 + (s)*4352)
#define PROJ_SMEM 84992

__global__ void __launch_bounds__(256) proj_mma(const float* __restrict__ unused) {
    extern __shared__ __half psm[];
    const uint32_t sb = smem_u32(psm);
    const int tid = threadIdx.x, wid = tid >> 5, lane = tid & 31;
    const int g = lane >> 2, t4 = lane & 3;
    const int lrow = lane & 15, lcol = (lane >> 4) * 8;
    const int b = blockIdx.z, co0 = blockIdx.y * 128, n0 = blockIdx.x * 128;

    const int wc = (wid & 3) * 32;
    const int wn = (wid >> 2) * 64;

    #define PSB(idx) (sb + (uint32_t)(idx) * 2u)

    {
        const __half* wsrc = g_Wh + (size_t)co0 * CC;
        #pragma unroll
        for (int r = 0; r < 16; r++) {
            int id = tid + 256*r, row = id >> 5, ch = (id & 31) * 8;
            cpa16(PSB(PW_O + row*LDW + ch), wsrc + (size_t)row*CC + ch);
        }
        const __half* xsrc = g_xh + ((size_t)b*CC + 0)*NPIX + n0;
        #pragma unroll
        for (int r = 0; r < 2; r++) {
            int id = tid + 256*r, k = id >> 4, ch = (id & 15) * 8;
            cpa16(PSB(PX_ST(0) + k*LDX + ch), xsrc + (size_t)k*NPIX + ch);
        }
        CP_COMMIT();
    }

    float acc[2][8][4];
    #pragma unroll
    for (int i = 0; i < 2; i++)
        #pragma unroll
        for (int j = 0; j < 8; j++)
            #pragma unroll
            for (int q = 0; q < 4; q++) acc[i][j][q] = 0.f;

    for (int kc = 0; kc < 8; ++kc) {
        const int buf = kc & 1;
        CP_WAIT0();
        __syncthreads();
        if (kc < 7) {
            const __half* xsrc = g_xh + ((size_t)b*CC + (kc+1)*32)*NPIX + n0;
            #pragma unroll
            for (int r = 0; r < 2; r++) {
                int id = tid + 256*r, k = id >> 4, ch = (id & 15) * 8;
                cpa16(PSB(PX_ST(buf^1) + k*LDX + ch), xsrc + (size_t)k*NPIX + ch);
            }
            CP_COMMIT();
        }
        const uint32_t XO = PX_ST(buf);
        #pragma unroll
        for (int ks = 0; ks < 2; ++ks) {
            const int kk = kc*32 + ks*16;
            uint32_t a0[4], a1[4];
            ldsm4(a0, PSB(PW_O + (wc      + lrow)*LDW + kk + lcol));
            ldsm4(a1, PSB(PW_O + (wc + 16 + lrow)*LDW + kk + lcol));
            #pragma unroll
            for (int nt = 0; nt < 4; ++nt) {
                uint32_t bx[4];
                ldsm4t(bx, PSB(XO + (ks*16 + lrow)*LDX + wn + nt*16 + lcol));
                mmah(acc[0][2*nt],   a0, bx[0], bx[1]);
                mmah(acc[0][2*nt+1], a0, bx[2], bx[3]);
                mmah(acc[1][2*nt],   a1, bx[0], bx[1]);
                mmah(acc[1][2*nt+1], a1, bx[2], bx[3]);
            }
        }
        __syncthreads();
    }

    if (co0 >= 128) {
        #pragma unroll
        for (int i = 0; i < 2; i++) {
            #pragma unroll
            for (int h = 0; h < 2; h++) {
                int col = wc + 16*i + g + 8*h;
                int c = co0 - 128 + col;
                float bias = g_ball[co0 + col];
                __half* dst = g_V + ((size_t)b*CC + c)*NPIX + n0;
                #pragma unroll
                for (int j = 0; j < 8; j++) {
                    int n = wn + 8*j + t4*2;
                    *(uint32_t*)(dst + n) =
                        packh(acc[i][j][2*h] + bias, acc[i][j][2*h+1] + bias);
                }
            }
        }
    } else {
        __syncthreads();
        #pragma unroll
        for (int i = 0; i < 2; i++)
            #pragma unroll
            for (int h = 0; h < 2; h++) {
                int col = wc + 16*i + g + 8*h;
                float bias = g_ball[col];
                #pragma unroll
                for (int j = 0; j < 8; j++) {
                    int n = wn + 8*j + t4*2;
                    psm[PW_O + n*LDT + col]     = __float2half(acc[i][j][2*h]   + bias);
                    psm[PW_O + (n+1)*LDT + col] = __float2half(acc[i][j][2*h+1] + bias);
                }
            }
        __syncthreads();
        #pragma unroll
        for (int r = 0; r < 8; r++) {
            int id = tid + 256*r, nl = id >> 4, ch = id & 15;
            uint4 v = *(uint4*)&psm[PW_O + nl*LDT + ch*8];
            size_t nglob = (size_t)b*NPIX + n0 + nl;
            if (ch < 8) *(uint4*)(g_Q + nglob*CQ + ch*8) = v;
            else        *(uint4*)(g_K + nglob*CQ + (ch-8)*8) = v;
        }
    }
}

// ===== Kernel 2: fused attention (R15 structure, running-pointer loads) ====
#define SM_K  0
#define SM_S  4608
#define Q_ST(s) (9216 + (s)*4608)
#define V_ST(s) (18432 + (s)*18432)
#define SMEM_HALVES (18432 + 2*18432)
#define SMEM_BYTES  (SMEM_HALVES*2)

__global__ void __launch_bounds__(256, 2) attn_mma(float* __restrict__ out,
                                                   const float* __restrict__ gbias) {
    extern __shared__ __half sm[];
    const uint32_t sb = smem_u32(sm);
    const int tid = threadIdx.x, wid = tid >> 5, lane = tid & 31;
    const int g = lane >> 2, t4 = lane & 3;
    const int b = blockIdx.y, m0 = blockIdx.x * 64;
    const int lrow = lane & 15, lcol = (lane >> 4) * 8;

    const int w1m = (wid & 1) * 32, w1n = (wid >> 1) * 16;   // GEMM1 [32m x 16n]
    const int w2c = (wid >> 1) * 64, w2m = (wid & 1) * 32;   // GEMM2 [64c x 32m]

    #define SMB(idx) (sb + (uint32_t)(idx) * 2u)

    // ---- per-thread running pointers / fixed smem offsets for staging ----
    const int qrow = tid >> 3, qch = (tid & 7) * 8;         // Q: 2 chunks (rows qrow, qrow+32)
    const __half* gq = g_Q + ((size_t)b*NPIX + qrow)*CQ + qch;
    const uint32_t qd0 = qrow*LD + qch, qd1 = (qrow+32)*LD + qch;
    const int vrow = tid >> 3, vch = (tid & 7) * 8;         // V: 8 chunks (rows vrow + 32r)
    const __half* gv = g_V + ((size_t)b*CC + vrow)*NPIX + vch;
    const uint32_t vd0 = vrow*LD + vch;

    {   // K prologue + stage 0 (one group)
        const __half* k = g_K + ((size_t)b*NPIX + m0)*CQ;
        #pragma unroll
        for (int r = 0; r < 2; r++) {
            int id = tid + 256*r, row = id >> 3, ch = (id & 7) * 8;
            cpa16(SMB(SM_K + row*LD + ch), k + (size_t)row*CQ + ch);
        }
        cpa16(SMB(Q_ST(0) + qd0), gq);
        cpa16(SMB(Q_ST(0) + qd1), gq + (size_t)32*CQ);
        #pragma unroll
        for (int r = 0; r < 8; r++)
            cpa16(SMB(V_ST(0) + vd0 + r*32*LD), gv + (size_t)r*32*NPIX);
        CP_COMMIT();
    }

    float acc[4][4][4];
    #pragma unroll
    for (int i = 0; i < 4; i++)
        #pragma unroll
        for (int j = 0; j < 4; j++)
            #pragma unroll
            for (int q = 0; q < 4; q++) acc[i][j][q] = 0.f;

    const __half* gq_n = gq + 64*CQ;   // pointers for next stage (advance 64 n per iter)
    const __half* gv_n = gv + 64;

    for (int it = 0; it < 64; ++it) {
        const int buf = it & 1;
        CP_WAIT0();
        __syncthreads();
        if (it < 63) {
            const uint32_t QN = Q_ST(buf ^ 1), VN = V_ST(buf ^ 1);
            cpa16(SMB(QN + qd0), gq_n);
            cpa16(SMB(QN + qd1), gq_n + (size_t)32*CQ);
            #pragma unroll
            for (int r = 0; r < 8; r++)
                cpa16(SMB(VN + vd0 + r*32*LD), gv_n + (size_t)r*32*NPIX);
            CP_COMMIT();
            gq_n += 64*CQ;
            gv_n += 64;
        }

        const uint32_t QO = Q_ST(buf), VO = V_ST(buf);

        // ---- GEMM1: S[m][n] = K·Q ----
        float sacc[2][2][4];
        #pragma unroll
        for (int i = 0; i < 2; i++)
            #pragma unroll
            for (int j = 0; j < 2; j++)
                #pragma unroll
                for (int q = 0; q < 4; q++) sacc[i][j][q] = 0.f;

        #pragma unroll
        for (int kk = 0; kk < 4; kk++) {
            const int C = kk * 16 + lcol;
            uint32_t k0[4], k1[4], qv[4];
            ldsm4(k0, SMB(SM_K + (w1m      + lrow)*LD + C));
            ldsm4(k1, SMB(SM_K + (w1m + 16 + lrow)*LD + C));
            ldsm4(qv, SMB(QO   + (w1n      + lrow)*LD + C));
            mmah(sacc[0][0], k0, qv[0], qv[2]);
            mmah(sacc[0][1], k0, qv[1], qv[3]);
            mmah(sacc[1][0], k1, qv[0], qv[2]);
            mmah(sacc[1][1], k1, qv[1], qv[3]);
        }

        // ---- elu + store S (fp16), layout [m][n] ----
        #pragma unroll
        for (int i = 0; i < 2; i++)
            #pragma unroll
            for (int j = 0; j < 2; j++) {
                int row = w1m + 16*i + g;
                int col = w1n + 8*j + t4*2;
                *(uint32_t*)&sm[SM_S + row*LD + col] =
                    packh(elu_raw(sacc[i][j][0]), elu_raw(sacc[i][j][1]));
                *(uint32_t*)&sm[SM_S + (row+8)*LD + col] =
                    packh(elu_raw(sacc[i][j][2]), elu_raw(sacc[i][j][3]));
            }
        __syncthreads();

        // ---- GEMM2: O[c][m] += V·S ----
        #pragma unroll
        for (int kk = 0; kk < 4; kk++) {
            const int C = kk * 16 + lcol;
            uint32_t vv[4][4], s0[4], s1[4];
            #pragma unroll
            for (int i = 0; i < 4; i++)
                ldsm4(vv[i], SMB(VO + (w2c + 16*i + lrow)*LD + C));
            ldsm4(s0, SMB(SM_S + (w2m      + lrow)*LD + C));
            ldsm4(s1, SMB(SM_S + (w2m + 16 + lrow)*LD + C));
            #pragma unroll
            for (int i = 0; i < 4; i++) {
                mmah(acc[i][0], vv[i], s0[0], s0[2]);
                mmah(acc[i][1], vv[i], s0[1], s0[3]);
                mmah(acc[i][2], vv[i], s1[0], s1[2]);
                mmah(acc[i][3], vv[i], s1[1], s1[3]);
            }
        }
    }

    // ---- epilogue: out = acc/4096 + gbias[c] ----
    const float inv = 1.0f / 4096.0f;
    #pragma unroll
    for (int i = 0; i < 4; i++) {
        int c  = w2c + 16*i + g;
        float b0 = gbias[c], b8 = gbias[c + 8];
        #pragma unroll
        for (int j = 0; j < 4; j++) {
            int m = m0 + w2m + 8*j + t4*2;
            float2 v0 = { fmaf(acc[i][j][0], inv, b0), fmaf(acc[i][j][1], inv, b0) };
            *(float2*)&out[((size_t)b*CC + c)*NPIX + m] = v0;
            float2 v1 = { fmaf(acc[i][j][2], inv, b8), fmaf(acc[i][j][3], inv, b8) };
            *(float2*)&out[((size_t)b*CC + c + 8)*NPIX + m] = v1;
        }
    }
}

// ================= launch =================
extern "C" void kernel_launch(void* const* d_in, const int* in_sizes, int n_in,
                              void* d_out, int out_size) {
    const float* x  = (const float*)d_in[0];
    const float* qw = (const float*)d_in[1];
    const float* qb = (const float*)d_in[2];
    const float* kw = (const float*)d_in[3];
    const float* kb = (const float*)d_in[4];
    const float* vw = (const float*)d_in[5];
    const float* vb = (const float*)d_in[6];
    const float* gw = (const float*)d_in[7];
    const float* gb = (const float*)d_in[8];
    float* out = (float*)d_out;

    cudaFuncSetAttribute(attn_mma, cudaFuncAttributeMaxDynamicSharedMemorySize, SMEM_BYTES);
    cudaFuncSetAttribute(proj_mma, cudaFuncAttributeMaxDynamicSharedMemorySize, PROJ_SMEM);

    prep_kernel<<<ROWS_ALL + 2048, 256>>>(x, qw, qb, kw, kb, vw, vb, gw);
    proj_mma<<<dim3(32, 3, BB), 256, PROJ_SMEM>>>(nullptr);
    attn_mma<<<dim3(64, BB), 256, SMEM_BYTES>>>(out, gb);
}